// round 1
// baseline (speedup 1.0000x reference)
#include <cuda_runtime.h>

#define N_TOK 2048
#define B_SZ  8
#define E_DIM 256
#define H_DIM 512
#define TOT_OUT ((size_t)N_TOK * B_SZ * H_DIM)   // 8388608

// Scratch (device globals — no allocations allowed)
__device__ float d_xn[(size_t)B_SZ * N_TOK * E_DIM];          // 16 MB, [b][n][e]
__device__ float d_S[(size_t)B_SZ * N_TOK * N_TOK];           // 134 MB, exp(scores)
__device__ float d_recip[B_SZ * N_TOK];                       // 1/rowsum
__device__ float d_partial[2048];
__device__ float d_inv;

// ---------------------------------------------------------------------------
__device__ __forceinline__ float blockReduceSum256(float v) {
    __shared__ float ws[8];
    __shared__ float tot;
    #pragma unroll
    for (int o = 16; o > 0; o >>= 1) v += __shfl_xor_sync(0xffffffffu, v, o);
    if ((threadIdx.x & 31) == 0) ws[threadIdx.x >> 5] = v;
    __syncthreads();
    if (threadIdx.x == 0) {
        float t = 0.f;
        #pragma unroll
        for (int i = 0; i < 8; i++) t += ws[i];
        tot = t;
    }
    __syncthreads();
    return tot;
}

// ---------------------------------------------------------------------------
// 1) normalize: xn[b][n][e] = x[n][b][e] / ||x[n][b]||
//    grid = N*B blocks (block = one (n,b) row), 256 threads = E
__global__ void normalize_k(const float* __restrict__ x) {
    const int row = blockIdx.x;          // row = n*B + b (input-contiguous)
    const int e   = threadIdx.x;
    float v = x[(size_t)row * E_DIM + e];
    float t = blockReduceSum256(v * v);
    float inv = rsqrtf(t);
    const int n = row / B_SZ, b = row % B_SZ;
    d_xn[((size_t)b * N_TOK + n) * E_DIM + e] = v * inv;
}

// ---------------------------------------------------------------------------
// 2) S[b][i][j] = exp( xn_i . xn_j )   — C = A*A^T, A: 2048x256 row-major
//    128x128 tile, BK=8, 8x8 per thread, 256 threads.
__global__ __launch_bounds__(256, 2) void gemm1_k() {
    const int b = blockIdx.z;
    const float* __restrict__ A = d_xn + (size_t)b * N_TOK * E_DIM;
    float* __restrict__ C = d_S + (size_t)b * N_TOK * N_TOK;

    __shared__ __align__(16) float As[8 * 128];
    __shared__ __align__(16) float Bs[8 * 128];

    const int tid  = threadIdx.x;
    const int cRow = blockIdx.y, cCol = blockIdx.x;

    const int innerRow = tid >> 1;          // 0..127
    const int innerCol = (tid & 1) * 4;     // 0 or 4
    const int threadRow = (tid >> 4) * 8;   // 0..120
    const int threadCol = (tid & 15) * 8;

    const float* Ap = A + (size_t)(cRow * 128 + innerRow) * E_DIM + innerCol;
    const float* Bp = A + (size_t)(cCol * 128 + innerRow) * E_DIM + innerCol;

    float acc[8][8] = {};
    for (int k0 = 0; k0 < E_DIM; k0 += 8) {
        float4 av = *(const float4*)(Ap + k0);
        float4 bv = *(const float4*)(Bp + k0);
        As[(innerCol + 0) * 128 + innerRow] = av.x;
        As[(innerCol + 1) * 128 + innerRow] = av.y;
        As[(innerCol + 2) * 128 + innerRow] = av.z;
        As[(innerCol + 3) * 128 + innerRow] = av.w;
        Bs[(innerCol + 0) * 128 + innerRow] = bv.x;
        Bs[(innerCol + 1) * 128 + innerRow] = bv.y;
        Bs[(innerCol + 2) * 128 + innerRow] = bv.z;
        Bs[(innerCol + 3) * 128 + innerRow] = bv.w;
        __syncthreads();
        float regM[8], regN[8];
        #pragma unroll
        for (int k = 0; k < 8; k++) {
            #pragma unroll
            for (int m = 0; m < 8; m++) regM[m] = As[k * 128 + threadRow + m];
            #pragma unroll
            for (int n = 0; n < 8; n++) regN[n] = Bs[k * 128 + threadCol + n];
            #pragma unroll
            for (int m = 0; m < 8; m++)
                #pragma unroll
                for (int n = 0; n < 8; n++)
                    acc[m][n] += regM[m] * regN[n];
        }
        __syncthreads();
    }
    #pragma unroll
    for (int m = 0; m < 8; m++) {
        const int row = cRow * 128 + threadRow + m;
        float* Crow = C + (size_t)row * N_TOK + cCol * 128 + threadCol;
        #pragma unroll
        for (int n = 0; n < 8; n++) Crow[n] = __expf(acc[m][n]);
    }
}

// ---------------------------------------------------------------------------
// 3) rowsum: recip[b*N+i] = 1 / sum_j S[b][i][j]
__global__ void rowsum_k() {
    const int row = blockIdx.x;              // b*N + i
    const float* Sp = d_S + (size_t)row * N_TOK;
    float s = 0.f;
    for (int j = threadIdx.x; j < N_TOK; j += 256) s += Sp[j];
    float t = blockReduceSum256(s);
    if (threadIdx.x == 0) d_recip[row] = 1.0f / t;
}

// ---------------------------------------------------------------------------
// 4) out[n][b][h] = recip * sum_j S[b][i][j] * h[j][b][h]
__global__ __launch_bounds__(256, 2) void gemm2_k(const float* __restrict__ hmat,
                                                  float* __restrict__ out) {
    const int b = blockIdx.z;
    const float* __restrict__ A = d_S + (size_t)b * N_TOK * N_TOK;

    __shared__ __align__(16) float As[8 * 128];
    __shared__ __align__(16) float Bs[8 * 128];

    const int tid  = threadIdx.x;
    const int cRow = blockIdx.y, cCol = blockIdx.x;

    const int aRow = tid >> 1;               // 0..127
    const int aCol = (tid & 1) * 4;
    const int bRow = tid >> 5;               // 0..7
    const int bCol = (tid & 31) * 4;         // 0..124
    const int threadRow = (tid >> 4) * 8;
    const int threadCol = (tid & 15) * 8;

    const float* Ap = A + (size_t)(cRow * 128 + aRow) * N_TOK + aCol;
    const size_t ldb = (size_t)B_SZ * H_DIM;
    const float* Bp = hmat + (size_t)b * H_DIM + (size_t)cCol * 128 + bCol;

    float acc[8][8] = {};
    for (int k0 = 0; k0 < N_TOK; k0 += 8) {
        float4 av = *(const float4*)(Ap + k0);
        float4 bv = *(const float4*)(Bp + (size_t)(k0 + bRow) * ldb);
        As[(aCol + 0) * 128 + aRow] = av.x;
        As[(aCol + 1) * 128 + aRow] = av.y;
        As[(aCol + 2) * 128 + aRow] = av.z;
        As[(aCol + 3) * 128 + aRow] = av.w;
        *(float4*)&Bs[bRow * 128 + bCol] = bv;
        __syncthreads();
        float regM[8], regN[8];
        #pragma unroll
        for (int k = 0; k < 8; k++) {
            #pragma unroll
            for (int m = 0; m < 8; m++) regM[m] = As[k * 128 + threadRow + m];
            #pragma unroll
            for (int n = 0; n < 8; n++) regN[n] = Bs[k * 128 + threadCol + n];
            #pragma unroll
            for (int m = 0; m < 8; m++)
                #pragma unroll
                for (int n = 0; n < 8; n++)
                    acc[m][n] += regM[m] * regN[n];
        }
        __syncthreads();
    }
    #pragma unroll
    for (int m = 0; m < 8; m++) {
        const int row = cRow * 128 + threadRow + m;
        const float r = d_recip[b * N_TOK + row];
        float* Orow = out + ((size_t)row * B_SZ + b) * H_DIM + cCol * 128 + threadCol;
        #pragma unroll
        for (int n = 0; n < 8; n++) Orow[n] = acc[m][n] * r;
    }
}

// ---------------------------------------------------------------------------
// 5) global-norm reduction (deterministic two-stage) + scale
__global__ void sumsq_k(const float* __restrict__ out) {
    float s = 0.f;
    for (size_t i = (size_t)blockIdx.x * 256 + threadIdx.x; i < TOT_OUT; i += (size_t)2048 * 256)
        s += out[i] * out[i];
    float t = blockReduceSum256(s);
    if (threadIdx.x == 0) d_partial[blockIdx.x] = t;
}

__global__ void finalize_k() {
    float s = 0.f;
    for (int i = threadIdx.x; i < 2048; i += 256) s += d_partial[i];
    float t = blockReduceSum256(s);
    if (threadIdx.x == 0) d_inv = rsqrtf(t);
}

__global__ void scale_k(float* __restrict__ out) {
    const float inv = d_inv;
    for (size_t i = (size_t)blockIdx.x * 256 + threadIdx.x; i < TOT_OUT; i += (size_t)2048 * 256)
        out[i] *= inv;
}

// ---------------------------------------------------------------------------
extern "C" void kernel_launch(void* const* d_in, const int* in_sizes, int n_in,
                              void* d_out, int out_size) {
    const float* x;
    const float* h;
    if (in_sizes[0] == N_TOK * B_SZ * E_DIM) {
        x = (const float*)d_in[0];
        h = (const float*)d_in[1];
    } else {
        x = (const float*)d_in[1];
        h = (const float*)d_in[0];
    }
    float* out = (float*)d_out;

    normalize_k<<<N_TOK * B_SZ, 256>>>(x);
    gemm1_k<<<dim3(N_TOK / 128, N_TOK / 128, B_SZ), 256>>>();
    rowsum_k<<<B_SZ * N_TOK, 256>>>();
    gemm2_k<<<dim3(H_DIM / 128, N_TOK / 128, B_SZ), 256>>>(h, out);
    sumsq_k<<<2048, 256>>>(out);
    finalize_k<<<1, 256>>>();
    scale_k<<<2048, 256>>>(out);
}

// round 4
// speedup vs baseline: 2.3028x; 2.3028x over previous
#include <cuda_runtime.h>
#include <cuda_bf16.h>

#define N_TOK 2048
#define B_SZ  8
#define E_DIM 256
#define H_DIM 512
#define TOT_OUT ((size_t)N_TOK * B_SZ * H_DIM)

// ---------------- scratch (device globals; no allocations allowed) ----------
__device__ __align__(128) __nv_bfloat16 d_xh[(size_t)B_SZ * N_TOK * E_DIM];
__device__ __align__(128) __nv_bfloat16 d_xl[(size_t)B_SZ * N_TOK * E_DIM];
__device__ __align__(128) __nv_bfloat16 d_Sh[(size_t)B_SZ * N_TOK * N_TOK];
__device__ __align__(128) __nv_bfloat16 d_Sl[(size_t)B_SZ * N_TOK * N_TOK];
__device__ __align__(128) __nv_bfloat16 d_hTh[(size_t)B_SZ * H_DIM * N_TOK];
__device__ __align__(128) __nv_bfloat16 d_hTl[(size_t)B_SZ * H_DIM * N_TOK];
__device__ float d_psum[(size_t)B_SZ * N_TOK * 16];
__device__ float d_recip[B_SZ * N_TOK];
__device__ float d_partial[2048];
__device__ float d_inv;

// ---------------- helpers ----------------------------------------------------
__device__ __forceinline__ unsigned smem_u32(const void* p) {
    unsigned a;
    asm("{ .reg .u64 t; cvta.to.shared.u64 t, %1; cvt.u32.u64 %0, t; }" : "=r"(a) : "l"(p));
    return a;
}
__device__ __forceinline__ void cp16(unsigned dst, const void* src) {
    asm volatile("cp.async.cg.shared.global [%0], [%1], 16;\n" :: "r"(dst), "l"(src));
}
#define CP_COMMIT() asm volatile("cp.async.commit_group;\n" ::: "memory")
#define LDSM_X4(r0, r1, r2, r3, addr) \
    asm volatile("ldmatrix.sync.aligned.m8n8.x4.shared.b16 {%0,%1,%2,%3}, [%4];" \
                 : "=r"(r0), "=r"(r1), "=r"(r2), "=r"(r3) : "r"(addr))
__device__ __forceinline__ void mma_bf16(float* c, const unsigned* a, const unsigned* b) {
    asm volatile(
        "mma.sync.aligned.m16n8k16.row.col.f32.bf16.bf16.f32 "
        "{%0,%1,%2,%3}, {%4,%5,%6,%7}, {%8,%9}, {%0,%1,%2,%3};"
        : "+f"(c[0]), "+f"(c[1]), "+f"(c[2]), "+f"(c[3])
        : "r"(a[0]), "r"(a[1]), "r"(a[2]), "r"(a[3]), "r"(b[0]), "r"(b[1]));
}
__device__ __forceinline__ unsigned pack_bf16(__nv_bfloat16 a, __nv_bfloat16 b) {
    return ((unsigned)__bfloat16_as_ushort(b) << 16) | (unsigned)__bfloat16_as_ushort(a);
}

// ---------------- SMEM layout ------------------------------------------------
#define LDS_ROW   40                       // elements per smem row (80 B, padded)
#define TILE_SM_B (128 * LDS_ROW * 2)      // 10240 B per 128x32 bf16 tile
#define STAGE_SM  (4 * TILE_SM_B)          // Ah, Al, Bh, Bl = 40960 B
#define SMEM_TOTAL (1024 + 2 * STAGE_SM)   // 82944 B

// ---------------- shared mainloop -------------------------------------------
// C(128x128) += A(128xK)*B(128xK)^T with split-bf16 (hh + hl + lh), K = NC*32.
template <int NC>
__device__ __forceinline__ void mma_mainloop(char* smem,
                                             const __nv_bfloat16* Ah, const __nv_bfloat16* Al,
                                             const __nv_bfloat16* Bh, const __nv_bfloat16* Bl,
                                             int sA, int sB, float acc[2][8][4]) {
    const int tid = threadIdx.x;
    const int lane = tid & 31, wid = tid >> 5;
    const int wm = wid >> 1, wn = wid & 1;
    const unsigned sbase = smem_u32(smem) + 1024;

    #pragma unroll
    for (int mt = 0; mt < 2; mt++)
        #pragma unroll
        for (int nt = 0; nt < 8; nt++)
            #pragma unroll
            for (int c = 0; c < 4; c++) acc[mt][nt][c] = 0.f;

    // stage loader: 4 tiles x 128 rows x 64B data (stride 80B in smem)
    auto load_stage = [&](int kc, int buf) {
        const unsigned st = sbase + buf * STAGE_SM;
        const int k0 = kc * 32;
        #pragma unroll
        for (int i = 0; i < 8; i++) {
            const int tile = i >> 1;
            const __nv_bfloat16* g = (tile == 0) ? Ah : (tile == 1) ? Al : (tile == 2) ? Bh : Bl;
            const int stride = (tile < 2) ? sA : sB;
            const int idx = (i & 1) * 256 + tid;
            const int row = idx >> 2, seg = idx & 3;
            cp16(st + tile * TILE_SM_B + row * 80 + seg * 16,
                 g + (size_t)row * stride + k0 + seg * 8);
        }
        CP_COMMIT();
    };

    load_stage(0, 0);
    for (int kc = 0; kc < NC; kc++) {
        if (kc + 1 < NC) {
            load_stage(kc + 1, (kc + 1) & 1);
            asm volatile("cp.async.wait_group 1;\n" ::: "memory");
        } else {
            asm volatile("cp.async.wait_group 0;\n" ::: "memory");
        }
        __syncthreads();

        const unsigned st  = sbase + (kc & 1) * STAGE_SM;
        const unsigned AbH = st, AbL = st + TILE_SM_B;
        const unsigned BbH = st + 2 * TILE_SM_B, BbL = st + 3 * TILE_SM_B;

        #pragma unroll
        for (int ks = 0; ks < 2; ks++) {
            const int k0e = ks * 16;
            unsigned ah[2][4], al[2][4], bh[8][2], bl[8][2];
            #pragma unroll
            for (int mt = 0; mt < 2; mt++) {
                const unsigned off =
                    ((wm * 32 + mt * 16 + (lane & 15)) * LDS_ROW + (lane >> 4) * 8 + k0e) * 2;
                LDSM_X4(ah[mt][0], ah[mt][1], ah[mt][2], ah[mt][3], AbH + off);
                LDSM_X4(al[mt][0], al[mt][1], al[mt][2], al[mt][3], AbL + off);
            }
            #pragma unroll
            for (int ng = 0; ng < 4; ng++) {
                const unsigned off =
                    ((wn * 64 + ng * 16 + (lane & 7) + ((lane >> 4) << 3)) * LDS_ROW +
                     ((lane >> 3) & 1) * 8 + k0e) * 2;
                LDSM_X4(bh[2 * ng][0], bh[2 * ng][1], bh[2 * ng + 1][0], bh[2 * ng + 1][1], BbH + off);
                LDSM_X4(bl[2 * ng][0], bl[2 * ng][1], bl[2 * ng + 1][0], bl[2 * ng + 1][1], BbL + off);
            }
            #pragma unroll
            for (int mt = 0; mt < 2; mt++)
                #pragma unroll
                for (int nt = 0; nt < 8; nt++) {
                    mma_bf16(acc[mt][nt], ah[mt], bh[nt]);
                    mma_bf16(acc[mt][nt], ah[mt], bl[nt]);
                    mma_bf16(acc[mt][nt], al[mt], bh[nt]);
                }
        }
        __syncthreads();
    }
}

// ---------------------------------------------------------------------------
// GEMM1: S = exp(Xn Xn^T) -> bf16 hi/lo + per-tile row partial sums.
__global__ __launch_bounds__(256, 1) void gemm1_k() {
    extern __shared__ __align__(1024) char smem[];
    const int tid = threadIdx.x;
    const int lane = tid & 31, wid = tid >> 5;
    const int wm = wid >> 1, wn = wid & 1;
    const int b = blockIdx.z, cRow = blockIdx.y, cCol = blockIdx.x;

    const __nv_bfloat16* Ah = d_xh + ((size_t)b * N_TOK + cRow * 128) * E_DIM;
    const __nv_bfloat16* Al = d_xl + ((size_t)b * N_TOK + cRow * 128) * E_DIM;
    const __nv_bfloat16* Bh = d_xh + ((size_t)b * N_TOK + cCol * 128) * E_DIM;
    const __nv_bfloat16* Bl = d_xl + ((size_t)b * N_TOK + cCol * 128) * E_DIM;

    float acc[2][8][4];
    mma_mainloop<E_DIM / 32>(smem, Ah, Al, Bh, Bl, E_DIM, E_DIM, acc);

    float* ps = (float*)smem;   // [128][2] row partials
    #pragma unroll
    for (int mt = 0; mt < 2; mt++) {
        const int r0 = wm * 32 + mt * 16 + (lane >> 2);
        float s0 = 0.f, s1 = 0.f;
        #pragma unroll
        for (int nt = 0; nt < 8; nt++) {
            float e0 = __expf(acc[mt][nt][0]);
            float e1 = __expf(acc[mt][nt][1]);
            float e2 = __expf(acc[mt][nt][2]);
            float e3 = __expf(acc[mt][nt][3]);
            s0 += e0 + e1;
            s1 += e2 + e3;
            __nv_bfloat16 h0 = __float2bfloat16(e0), h1 = __float2bfloat16(e1);
            __nv_bfloat16 h2 = __float2bfloat16(e2), h3 = __float2bfloat16(e3);
            __nv_bfloat16 l0 = __float2bfloat16(e0 - __bfloat162float(h0));
            __nv_bfloat16 l1 = __float2bfloat16(e1 - __bfloat162float(h1));
            __nv_bfloat16 l2 = __float2bfloat16(e2 - __bfloat162float(h2));
            __nv_bfloat16 l3 = __float2bfloat16(e3 - __bfloat162float(h3));
            const int col = cCol * 128 + wn * 64 + nt * 8 + (lane & 3) * 2;
            const size_t o0 = ((size_t)b * N_TOK + cRow * 128 + r0) * N_TOK + col;
            const size_t o1 = o0 + (size_t)8 * N_TOK;
            *(unsigned*)(d_Sh + o0) = pack_bf16(h0, h1);
            *(unsigned*)(d_Sl + o0) = pack_bf16(l0, l1);
            *(unsigned*)(d_Sh + o1) = pack_bf16(h2, h3);
            *(unsigned*)(d_Sl + o1) = pack_bf16(l2, l3);
        }
        s0 += __shfl_xor_sync(0xffffffffu, s0, 1);
        s0 += __shfl_xor_sync(0xffffffffu, s0, 2);
        s1 += __shfl_xor_sync(0xffffffffu, s1, 1);
        s1 += __shfl_xor_sync(0xffffffffu, s1, 2);
        if ((lane & 3) == 0) {
            ps[r0 * 2 + wn] = s0;
            ps[(r0 + 8) * 2 + wn] = s1;
        }
    }
    __syncthreads();
    if (tid < 128)
        d_psum[((size_t)b * N_TOK + cRow * 128 + tid) * 16 + cCol] = ps[tid * 2] + ps[tid * 2 + 1];
}

// ---------------------------------------------------------------------------
// GEMM2: out = (1/rowsum) * S * H      (S hi/lo  x  hT hi/lo)
__global__ __launch_bounds__(256, 1) void gemm2_k(float* __restrict__ out) {
    extern __shared__ __align__(1024) char smem[];
    const int tid = threadIdx.x;
    const int lane = tid & 31, wid = tid >> 5;
    const int wm = wid >> 1, wn = wid & 1;
    const int b = blockIdx.z, cRow = blockIdx.y, cCol = blockIdx.x;

    const __nv_bfloat16* Ah = d_Sh + ((size_t)b * N_TOK + cRow * 128) * N_TOK;
    const __nv_bfloat16* Al = d_Sl + ((size_t)b * N_TOK + cRow * 128) * N_TOK;
    const __nv_bfloat16* Bh = d_hTh + ((size_t)b * H_DIM + cCol * 128) * N_TOK;
    const __nv_bfloat16* Bl = d_hTl + ((size_t)b * H_DIM + cCol * 128) * N_TOK;

    float acc[2][8][4];
    mma_mainloop<N_TOK / 32>(smem, Ah, Al, Bh, Bl, N_TOK, N_TOK, acc);

    #pragma unroll
    for (int mt = 0; mt < 2; mt++) {
        const int r0 = wm * 32 + mt * 16 + (lane >> 2);
        const int gr0 = cRow * 128 + r0;
        const float rc0 = d_recip[b * N_TOK + gr0];
        const float rc1 = d_recip[b * N_TOK + gr0 + 8];
        #pragma unroll
        for (int nt = 0; nt < 8; nt++) {
            const int col = cCol * 128 + wn * 64 + nt * 8 + (lane & 3) * 2;
            float2 v0 = make_float2(acc[mt][nt][0] * rc0, acc[mt][nt][1] * rc0);
            float2 v1 = make_float2(acc[mt][nt][2] * rc1, acc[mt][nt][3] * rc1);
            *(float2*)(out + ((size_t)gr0 * B_SZ + b) * H_DIM + col) = v0;
            *(float2*)(out + ((size_t)(gr0 + 8) * B_SZ + b) * H_DIM + col) = v1;
        }
    }
}

// ---------------------------------------------------------------------------
__device__ __forceinline__ float blockReduceSum256(float v) {
    __shared__ float ws[8];
    __shared__ float tot;
    #pragma unroll
    for (int o = 16; o > 0; o >>= 1) v += __shfl_xor_sync(0xffffffffu, v, o);
    if ((threadIdx.x & 31) == 0) ws[threadIdx.x >> 5] = v;
    __syncthreads();
    if (threadIdx.x == 0) {
        float t = 0.f;
        #pragma unroll
        for (int i = 0; i < 8; i++) t += ws[i];
        tot = t;
    }
    __syncthreads();
    return tot;
}

// normalize + split to bf16 hi/lo
__global__ void normalize_k(const float* __restrict__ x) {
    const int row = blockIdx.x;          // n*B + b
    const int e = threadIdx.x;
    float v = x[(size_t)row * E_DIM + e];
    float t = blockReduceSum256(v * v);
    float xn = v * rsqrtf(t);
    const int n = row / B_SZ, b = row % B_SZ;
    size_t o = ((size_t)b * N_TOK + n) * E_DIM + e;
    __nv_bfloat16 h = __float2bfloat16(xn);
    d_xh[o] = h;
    d_xl[o] = __float2bfloat16(xn - __bfloat162float(h));
}

// transpose h -> hT[b][hcol][n] with bf16 hi/lo split
__global__ void transpose_h_k(const float* __restrict__ h) {
    __shared__ float t[32][33];
    const int b = blockIdx.z, hc0 = blockIdx.y * 32, n0 = blockIdx.x * 32;
    const int tx = threadIdx.x, ty = threadIdx.y;
    #pragma unroll
    for (int r = ty; r < 32; r += 8)
        t[r][tx] = h[((size_t)(n0 + r) * B_SZ + b) * H_DIM + hc0 + tx];
    __syncthreads();
    #pragma unroll
    for (int r = ty; r < 32; r += 8) {
        float v = t[tx][r];
        size_t o = ((size_t)b * H_DIM + hc0 + r) * N_TOK + n0 + tx;
        __nv_bfloat16 hh = __float2bfloat16(v);
        d_hTh[o] = hh;
        d_hTl[o] = __float2bfloat16(v - __bfloat162float(hh));
    }
}

// rowsum partial reduce -> reciprocal
__global__ void recip_k() {
    int i = blockIdx.x * 256 + threadIdx.x;
    if (i < B_SZ * N_TOK) {
        const float* p = d_psum + (size_t)i * 16;
        float s = 0.f;
        #pragma unroll
        for (int t = 0; t < 16; t++) s += p[t];
        d_recip[i] = 1.0f / s;
    }
}

// global-norm reduction + scale
__global__ void sumsq_k(const float* __restrict__ out) {
    float s = 0.f;
    for (size_t i = (size_t)blockIdx.x * 256 + threadIdx.x; i < TOT_OUT; i += (size_t)2048 * 256)
        s += out[i] * out[i];
    float t = blockReduceSum256(s);
    if (threadIdx.x == 0) d_partial[blockIdx.x] = t;
}
__global__ void finalize_k() {
    float s = 0.f;
    for (int i = threadIdx.x; i < 2048; i += 256) s += d_partial[i];
    float t = blockReduceSum256(s);
    if (threadIdx.x == 0) d_inv = rsqrtf(t);
}
__global__ void scale_k(float* __restrict__ out) {
    const float inv = d_inv;
    for (size_t i = (size_t)blockIdx.x * 256 + threadIdx.x; i < TOT_OUT; i += (size_t)2048 * 256)
        out[i] *= inv;
}

// ---------------------------------------------------------------------------
extern "C" void kernel_launch(void* const* d_in, const int* in_sizes, int n_in,
                              void* d_out, int out_size) {
    const float* x;
    const float* h;
    if (in_sizes[0] == N_TOK * B_SZ * E_DIM) {
        x = (const float*)d_in[0];
        h = (const float*)d_in[1];
    } else {
        x = (const float*)d_in[1];
        h = (const float*)d_in[0];
    }
    float* out = (float*)d_out;

    cudaFuncSetAttribute(gemm1_k, cudaFuncAttributeMaxDynamicSharedMemorySize, SMEM_TOTAL);
    cudaFuncSetAttribute(gemm2_k, cudaFuncAttributeMaxDynamicSharedMemorySize, SMEM_TOTAL);

    normalize_k<<<N_TOK * B_SZ, 256>>>(x);
    transpose_h_k<<<dim3(N_TOK / 32, H_DIM / 32, B_SZ), dim3(32, 8)>>>(h);
    gemm1_k<<<dim3(16, 16, B_SZ), 256, SMEM_TOTAL>>>();
    recip_k<<<(B_SZ * N_TOK + 255) / 256, 256>>>();
    gemm2_k<<<dim3(4, 16, B_SZ), 256, SMEM_TOTAL>>>(out);
    sumsq_k<<<2048, 256>>>(out);
    finalize_k<<<1, 256>>>();
    scale_k<<<2048, 256>>>(out);
}